// round 4
// baseline (speedup 1.0000x reference)
#include <cuda_runtime.h>
#include <cuda_bf16.h>
#include <cuda_fp16.h>
#include <cstdint>

#define N_NODES 50000
#define N_EDGES 400000
#define IN_C 128
#define HID 256

// ---------------- scratch (device globals) ---------------------------------
__device__ float  g_proj [(size_t)N_NODES * 512];   // cols 0-255 src-proj, 256-511 dst-proj
__device__ float  g_agg  [(size_t)N_NODES * 256];
__device__ float  g_h    [(size_t)N_NODES * 256];
__device__ float  g_h2   [(size_t)N_NODES * 256];
__device__ __half g_eproj[(size_t)N_EDGES * 256];   // per-edge attr projection (+bias), CSR order
__device__ float  g_eaperm[(size_t)N_EDGES * 32];   // edge_attr permuted to CSR order
__device__ int g_srcperm[N_EDGES];
__device__ int g_deg[N_NODES], g_rowptr[N_NODES + 1], g_cursor[N_NODES], g_eids[N_EDGES];

// ---------------- CSR build ------------------------------------------------
__global__ void zero_deg_kernel(int* deg, int n) {
    for (int i = blockIdx.x * blockDim.x + threadIdx.x; i < n; i += gridDim.x * blockDim.x)
        deg[i] = 0;
}
__global__ void count_deg_kernel(const int* __restrict__ dst, int* deg, int e) {
    for (int i = blockIdx.x * blockDim.x + threadIdx.x; i < e; i += gridDim.x * blockDim.x)
        atomicAdd(&deg[dst[i]], 1);
}
// single-block exclusive scan, warp-shuffle based
__global__ void scan_kernel(const int* __restrict__ deg, int* rowptr, int* cursor, int n) {
    __shared__ int wsum[32];
    __shared__ int carry;
    int tid = threadIdx.x, lane = tid & 31, wid = tid >> 5;
    if (tid == 0) { carry = 0; rowptr[0] = 0; }
    __syncthreads();
    for (int base = 0; base < n; base += 1024) {
        int i = base + tid;
        int v = (i < n) ? deg[i] : 0;
        int cr = carry;
        // warp inclusive scan
        int x = v;
        #pragma unroll
        for (int off = 1; off < 32; off <<= 1) {
            int t = __shfl_up_sync(0xFFFFFFFFu, x, off);
            if (lane >= off) x += t;
        }
        if (lane == 31) wsum[wid] = x;
        __syncthreads();
        if (wid == 0) {
            int s = wsum[lane];
            #pragma unroll
            for (int off = 1; off < 32; off <<= 1) {
                int t = __shfl_up_sync(0xFFFFFFFFu, s, off);
                if (lane >= off) s += t;
            }
            wsum[lane] = s;
        }
        __syncthreads();
        int warp_off = (wid > 0) ? wsum[wid - 1] : 0;
        int inc = x + warp_off + cr;
        if (i < n) { rowptr[i + 1] = inc; cursor[i] = inc - v; }
        __syncthreads();
        if (tid == 1023) carry = inc;
        __syncthreads();
    }
}
__global__ void scatter_kernel(const int* __restrict__ dst, int* cursor, int* eids, int e) {
    for (int i = blockIdx.x * blockDim.x + threadIdx.x; i < e; i += gridDim.x * blockDim.x) {
        int p = atomicAdd(&cursor[dst[i]], 1);
        eids[p] = i;
    }
}

// ---------------- permute edge_attr + src into CSR order -------------------
__global__ void permute_ea_kernel(const float* __restrict__ ea, const int* __restrict__ eids,
                                  float* __restrict__ ea_perm, int e) {
    int total = e * 8;
    for (int g = blockIdx.x * blockDim.x + threadIdx.x; g < total; g += gridDim.x * blockDim.x) {
        int p = g >> 3, q = (g & 7) << 2;
        int src_e = eids[p];
        *(float4*)(ea_perm + (size_t)p * 32 + q) = *(const float4*)(ea + (size_t)src_e * 32 + q);
    }
}
__global__ void permute_src_kernel(const int* __restrict__ src, const int* __restrict__ eids,
                                   int* __restrict__ src_perm, int e) {
    for (int i = blockIdx.x * blockDim.x + threadIdx.x; i < e; i += gridDim.x * blockDim.x)
        src_perm[i] = src[eids[i]];
}

// ---------------- bf16 split helpers ---------------------------------------
__device__ __forceinline__ void pack2(float a, float b, uint32_t& hi, uint32_t& lo) {
    __nv_bfloat162 h = __floats2bfloat162_rn(a, b);
    float ra = a - __low2float(h);
    float rb = b - __high2float(h);
    __nv_bfloat162 l = __floats2bfloat162_rn(ra, rb);
    hi = *reinterpret_cast<uint32_t*>(&h);
    lo = *reinterpret_cast<uint32_t*>(&l);
}
__device__ __forceinline__ void mma_bf16(float* c, const uint32_t* a, const uint32_t* b) {
    asm volatile(
        "mma.sync.aligned.m16n8k16.row.col.f32.bf16.bf16.f32 "
        "{%0,%1,%2,%3}, {%4,%5,%6,%7}, {%8,%9}, {%0,%1,%2,%3};"
        : "+f"(c[0]), "+f"(c[1]), "+f"(c[2]), "+f"(c[3])
        : "r"(a[0]), "r"(a[1]), "r"(a[2]), "r"(a[3]), "r"(b[0]), "r"(b[1]));
}

// ---------------- 3-term bf16 tensor-core GEMM ------------------------------
// C = act(bias + A1@B1 + A2@B2). A fp32 row-major [M,K]; B fp32 row-major [K,256].
// CTA tile 128(M) x 128(N). grid.y: bit0 = n-half; bit1 selects (B1a,col 0..255)
// vs (B1b,col 256..511) for merged dual-output launches.
// smem layout (u32 units): sA[row*36 + kp] hi (kp 0..15), +16 lo. sB[kp*264 + n] hi, +132 lo.
template<typename OutT>
__global__ __launch_bounds__(256, 2) void gemm_bf3(
    const float* __restrict__ A1, int K1,
    const float* __restrict__ B1a, const float* __restrict__ B1b,
    const float* __restrict__ A2, int K2, const float* __restrict__ B2,
    const float* __restrict__ bias, int relu_flag,
    OutT* __restrict__ C, int ldc, int M)
{
    __shared__ uint32_t sA[128 * 36];
    __shared__ uint32_t sB[16 * 264];

    int tid = threadIdx.x, wid = tid >> 5, lane = tid & 31;
    int bm = blockIdx.x * 128;
    int yy = blockIdx.y;
    int bn = (yy & 1) * 128;
    int col_off = (yy >> 1) * 256;
    const float* B1 = (yy >= 2) ? B1b : B1a;
    int wm = (wid >> 2) * 64;
    int wn = (wid & 3) * 32;
    int gq = lane >> 2, tq = lane & 3;

    float acc[4][4][4];
    #pragma unroll
    for (int mi = 0; mi < 4; mi++)
        #pragma unroll
        for (int ni = 0; ni < 4; ni++)
            #pragma unroll
            for (int q = 0; q < 4; q++) acc[mi][ni][q] = 0.f;

    #pragma unroll 1
    for (int seg = 0; seg < 2; ++seg) {
        const float* A = seg ? A2 : A1;
        const float* B = seg ? B2 : B1;
        int K = seg ? K2 : K1;
        if (A == nullptr || K == 0) continue;

        #pragma unroll 1
        for (int k0 = 0; k0 < K; k0 += 32) {
            __syncthreads();
            // stage A [128][32] fp32 -> bf16 hi/lo pairs
            #pragma unroll
            for (int it = 0; it < 4; ++it) {
                int g = tid + it * 256;
                int row = g >> 3, c4 = (g & 7) << 2;
                int grow = bm + row;
                float4 v = make_float4(0.f, 0.f, 0.f, 0.f);
                if (grow < M) v = *(const float4*)(A + (size_t)grow * K + k0 + c4);
                uint32_t h0, l0, h1, l1;
                pack2(v.x, v.y, h0, l0);
                pack2(v.z, v.w, h1, l1);
                int base = row * 36 + (c4 >> 1);
                *(uint2*)&sA[base]      = make_uint2(h0, h1);
                *(uint2*)&sA[base + 16] = make_uint2(l0, l1);
            }
            // stage B [32][128] fp32 -> bf16 k-pairs (k, k+1 packed per u32)
            #pragma unroll
            for (int it = 0; it < 2; ++it) {
                int g = tid + it * 256;
                int kp = g >> 5, ng = (g & 31) << 2;
                const float* bp = B + (size_t)(k0 + kp * 2) * 256 + bn + ng;
                float4 u = *(const float4*)bp;
                float4 w = *(const float4*)(bp + 256);
                uint32_t h0, l0, h1, l1, h2, l2, h3, l3;
                pack2(u.x, w.x, h0, l0);
                pack2(u.y, w.y, h1, l1);
                pack2(u.z, w.z, h2, l2);
                pack2(u.w, w.w, h3, l3);
                int base = kp * 264 + ng;
                *(uint4*)&sB[base]       = make_uint4(h0, h1, h2, h3);
                *(uint4*)&sB[base + 132] = make_uint4(l0, l1, l2, l3);
            }
            __syncthreads();

            #pragma unroll
            for (int ks = 0; ks < 2; ++ks) {
                int kb = ks * 8;
                uint32_t bh[4][2], bl[4][2];
                #pragma unroll
                for (int ni = 0; ni < 4; ni++) {
                    int cn = wn + ni * 8 + gq;
                    bh[ni][0] = sB[(kb + tq) * 264 + cn];
                    bh[ni][1] = sB[(kb + 4 + tq) * 264 + cn];
                    bl[ni][0] = sB[(kb + tq) * 264 + 132 + cn];
                    bl[ni][1] = sB[(kb + 4 + tq) * 264 + 132 + cn];
                }
                #pragma unroll
                for (int mi = 0; mi < 4; mi++) {
                    int r0 = wm + mi * 16 + gq;
                    uint32_t ah[4], al[4];
                    ah[0] = sA[r0 * 36 + kb + tq];
                    ah[1] = sA[(r0 + 8) * 36 + kb + tq];
                    ah[2] = sA[r0 * 36 + kb + 4 + tq];
                    ah[3] = sA[(r0 + 8) * 36 + kb + 4 + tq];
                    al[0] = sA[r0 * 36 + 16 + kb + tq];
                    al[1] = sA[(r0 + 8) * 36 + 16 + kb + tq];
                    al[2] = sA[r0 * 36 + 16 + kb + 4 + tq];
                    al[3] = sA[(r0 + 8) * 36 + 16 + kb + 4 + tq];
                    #pragma unroll
                    for (int ni = 0; ni < 4; ni++) {
                        mma_bf16(acc[mi][ni], ah, bh[ni]);   // hi*hi
                        mma_bf16(acc[mi][ni], ah, bl[ni]);   // hi*lo
                        mma_bf16(acc[mi][ni], al, bh[ni]);   // lo*hi
                    }
                }
            }
        }
    }

    // epilogue
    #pragma unroll
    for (int mi = 0; mi < 4; mi++) {
        int r = bm + wm + mi * 16 + gq;
        #pragma unroll
        for (int ni = 0; ni < 4; ni++) {
            int cc = wn + ni * 8 + tq * 2;
            int gcol = bn + cc;          // 0..255 within this output block
            float b0 = 0.f, b1 = 0.f;
            if (bias) { b0 = __ldg(bias + gcol); b1 = __ldg(bias + gcol + 1); }
            float v0 = acc[mi][ni][0] + b0, v1 = acc[mi][ni][1] + b1;
            float v2 = acc[mi][ni][2] + b0, v3 = acc[mi][ni][3] + b1;
            if (relu_flag) {
                v0 = fmaxf(v0, 0.f); v1 = fmaxf(v1, 0.f);
                v2 = fmaxf(v2, 0.f); v3 = fmaxf(v3, 0.f);
            }
            size_t o0 = (size_t)r * ldc + col_off + gcol;
            size_t o1 = (size_t)(r + 8) * ldc + col_off + gcol;
            if constexpr (sizeof(OutT) == 4) {
                if (r < M)     *(float2*)((float*)C + o0) = make_float2(v0, v1);
                if (r + 8 < M) *(float2*)((float*)C + o1) = make_float2(v2, v3);
            } else {
                if (r < M)     *(__half2*)((__half*)C + o0) = __floats2half2_rn(v0, v1);
                if (r + 8 < M) *(__half2*)((__half*)C + o1) = __floats2half2_rn(v2, v3);
            }
        }
    }
}

// ---------------- edge aggregation (CSR order, fp16 eproj) ------------------
__global__ __launch_bounds__(256) void agg_kernel(
    const float* __restrict__ proj, const __half* __restrict__ eproj,
    const int* __restrict__ src_perm, const int* __restrict__ rowptr,
    float* __restrict__ agg, int n)
{
    int tid = threadIdx.x;
    for (int node = blockIdx.x; node < n; node += gridDim.x) {
        int beg = rowptr[node], end = rowptr[node + 1];
        float bdst = proj[(size_t)node * 512 + 256 + tid];
        float acc = 0.f;
        int p = beg;
        for (; p + 4 <= end; p += 4) {
            int s0 = src_perm[p],     s1 = src_perm[p + 1];
            int s2 = src_perm[p + 2], s3 = src_perm[p + 3];
            float a0 = proj[(size_t)s0 * 512 + tid] + __half2float(eproj[(size_t)p * 256 + tid]);
            float a1 = proj[(size_t)s1 * 512 + tid] + __half2float(eproj[(size_t)(p + 1) * 256 + tid]);
            float a2 = proj[(size_t)s2 * 512 + tid] + __half2float(eproj[(size_t)(p + 2) * 256 + tid]);
            float a3 = proj[(size_t)s3 * 512 + tid] + __half2float(eproj[(size_t)(p + 3) * 256 + tid]);
            acc += fmaxf(a0 + bdst, 0.f) + fmaxf(a1 + bdst, 0.f)
                 + fmaxf(a2 + bdst, 0.f) + fmaxf(a3 + bdst, 0.f);
        }
        for (; p < end; ++p) {
            float a = proj[(size_t)src_perm[p] * 512 + tid] + __half2float(eproj[(size_t)p * 256 + tid]);
            acc += fmaxf(a + bdst, 0.f);
        }
        agg[(size_t)node * 256 + tid] = acc / fmaxf((float)(end - beg), 1.f);
    }
}

// ---------------- final head -----------------------------------------------
__global__ void head2_kernel(const float* __restrict__ h,
                             const float* __restrict__ w,
                             const float* __restrict__ b,
                             float* __restrict__ out, int n)
{
    int warp = (blockIdx.x * blockDim.x + threadIdx.x) >> 5;
    int lane = threadIdx.x & 31;
    if (warp >= n) return;
    float s = 0.f;
    #pragma unroll
    for (int c = lane; c < 256; c += 32)
        s += h[(size_t)warp * 256 + c] * w[c];
    #pragma unroll
    for (int off = 16; off; off >>= 1) s += __shfl_xor_sync(0xFFFFFFFFu, s, off);
    if (lane == 0) out[warp] = s + b[0];
}

// ---------------- launch ---------------------------------------------------
extern "C" void kernel_launch(void* const* d_in, const int* in_sizes, int n_in,
                              void* d_out, int out_size)
{
    const float* x   = (const float*)d_in[0];
    const int*   ei  = (const int*)  d_in[1];
    const float* ea  = (const float*)d_in[2];
    const float* e0w = (const float*)d_in[3];
    const float* e0b = (const float*)d_in[4];
    const float* n0w = (const float*)d_in[5];
    const float* n0b = (const float*)d_in[6];
    const float* ew  = (const float*)d_in[7];   // [2, 544, 256]
    const float* ebb = (const float*)d_in[8];   // [2, 256]
    const float* nw  = (const float*)d_in[9];   // [2, 512, 256]
    const float* nb  = (const float*)d_in[10];  // [2, 256]
    const float* h1w = (const float*)d_in[11];
    const float* h1b = (const float*)d_in[12];
    const float* h2w = (const float*)d_in[13];
    const float* h2b = (const float*)d_in[14];
    float* out = (float*)d_out;

    float *proj, *agg, *h, *h2, *eaperm;
    __half* eproj;
    int *deg, *rowptr, *cursor, *eids, *srcperm;
    cudaGetSymbolAddress((void**)&proj,    g_proj);
    cudaGetSymbolAddress((void**)&agg,     g_agg);
    cudaGetSymbolAddress((void**)&h,       g_h);
    cudaGetSymbolAddress((void**)&h2,      g_h2);
    cudaGetSymbolAddress((void**)&eproj,   g_eproj);
    cudaGetSymbolAddress((void**)&eaperm,  g_eaperm);
    cudaGetSymbolAddress((void**)&srcperm, g_srcperm);
    cudaGetSymbolAddress((void**)&deg,     g_deg);
    cudaGetSymbolAddress((void**)&rowptr,  g_rowptr);
    cudaGetSymbolAddress((void**)&cursor,  g_cursor);
    cudaGetSymbolAddress((void**)&eids,    g_eids);

    const int* src = ei;
    const int* dst = ei + N_EDGES;

    // --- CSR build + permutation (once, reused by all 3 layers) ---
    zero_deg_kernel<<<200, 256>>>(deg, N_NODES);
    count_deg_kernel<<<1024, 256>>>(dst, deg, N_EDGES);
    scan_kernel<<<1, 1024>>>(deg, rowptr, cursor, N_NODES);
    scatter_kernel<<<1024, 256>>>(dst, cursor, eids, N_EDGES);
    permute_ea_kernel<<<2048, 256>>>(ea, eids, eaperm, N_EDGES);
    permute_src_kernel<<<1024, 256>>>(src, eids, srcperm, N_EDGES);

    const int NODE_GRID = (N_NODES + 127) / 128;   // 391
    const int EDGE_GRID = N_EDGES / 128;           // 3125
    const int AGG_BLOCKS = 2048;
    dim3 pgrid(NODE_GRID, 4);   // merged src+dst projections
    dim3 ngrid(NODE_GRID, 2);
    dim3 egrid(EDGE_GRID, 2);

    // ================= layer 0 =================
    gemm_bf3<float><<<pgrid, 256>>>(x, IN_C, e0w, e0w + (size_t)IN_C * 256,
                                    nullptr, 0, nullptr,
                                    nullptr, 0, proj, 512, N_NODES);
    gemm_bf3<__half><<<egrid, 256>>>(eaperm, 32, e0w + (size_t)2 * IN_C * 256, nullptr,
                                     nullptr, 0, nullptr,
                                     e0b, 0, eproj, 256, N_EDGES);
    agg_kernel<<<AGG_BLOCKS, 256>>>(proj, eproj, srcperm, rowptr, agg, N_NODES);
    gemm_bf3<float><<<ngrid, 256>>>(x, IN_C, n0w, nullptr,
                                    agg, HID, n0w + (size_t)IN_C * 256,
                                    n0b, 1, h, 256, N_NODES);

    // ================= layers 1..2 =================
    float* h_cur = h;
    float* h_nxt = h2;
    for (int i = 0; i < 2; ++i) {
        const float* ewi = ew + (size_t)i * 544 * 256;
        const float* ebi = ebb + (size_t)i * 256;
        const float* nwi = nw + (size_t)i * 512 * 256;
        const float* nbi = nb + (size_t)i * 256;

        gemm_bf3<float><<<pgrid, 256>>>(h_cur, HID, ewi, ewi + (size_t)HID * 256,
                                        nullptr, 0, nullptr,
                                        nullptr, 0, proj, 512, N_NODES);
        gemm_bf3<__half><<<egrid, 256>>>(eaperm, 32, ewi + (size_t)2 * HID * 256, nullptr,
                                         nullptr, 0, nullptr,
                                         ebi, 0, eproj, 256, N_EDGES);
        agg_kernel<<<AGG_BLOCKS, 256>>>(proj, eproj, srcperm, rowptr, agg, N_NODES);
        gemm_bf3<float><<<ngrid, 256>>>(h_cur, HID, nwi, nullptr,
                                        agg, HID, nwi + (size_t)HID * 256,
                                        nbi, 1, h_nxt, 256, N_NODES);
        float* t = h_cur; h_cur = h_nxt; h_nxt = t;
    }

    // ================= head =================
    gemm_bf3<float><<<ngrid, 256>>>(h_cur, HID, h1w, nullptr,
                                    nullptr, 0, nullptr,
                                    h1b, 1, h_nxt, 256, N_NODES);
    head2_kernel<<<(N_NODES * 32 + 255) / 256, 256>>>(h_nxt, h2w, h2b, out, N_NODES);
}